// round 11
// baseline (speedup 1.0000x reference)
#include <cuda_runtime.h>
#include <cuda_fp16.h>
#include <math.h>
#include <stdint.h>

#define NN 50000
#define EE 800000
#define DD 128
#define OUTC 64
#define NB 49                      // build-kernel blocks (all-resident on 148 SMs)
#define NTH 1024

typedef unsigned long long u64;

// ---------------- scratch (device globals; no allocation allowed) ----------
__device__ int   g_ei_is64;
__device__ int   g_m_is32;
__device__ unsigned char g_M[NN * DD];
__device__ int   g_deg[NN];
__device__ float g_dinv[NN];
__device__ int   g_off[NN + 1];
__device__ int   g_cur[NN];
__device__ int   g_bsum[64];
__device__ int   g_barc;            // grid-barrier counter (zeroed per launch)
__device__ int   g_src[EE];
__device__ __half g_xt[NN * DD];    // x_tilde, fp16, pre-scaled by dinv[row]
__device__ float g_agg[NN * DD];    // aggregated messages (fp32)
__device__ float g_h[NN * DD];      // layer-3 activations

// ---------------- f32x2 packed math ----------------------------------------
__device__ __forceinline__ u64 pack2(float s) {
    u64 d;
    asm("mov.b64 %0, {%1, %1};" : "=l"(d) : "f"(s));
    return d;
}
__device__ __forceinline__ void fma2(u64& acc, u64 a, u64 b) {
    asm("fma.rn.f32x2 %0, %1, %2, %0;" : "+l"(acc) : "l"(a), "l"(b));
}
__device__ __forceinline__ float2 unpack2(u64 v) {
    float lo, hi;
    asm("mov.b64 {%0, %1}, %2;" : "=f"(lo), "=f"(hi) : "l"(v));
    return make_float2(lo, hi);
}

// ---------------- software grid barrier (all blocks resident) ---------------
__device__ __forceinline__ void gbar(int target) {
    __syncthreads();
    if (threadIdx.x == 0) {
        __threadfence();
        atomicAdd(&g_barc, 1);
        while (*((volatile int*)&g_barc) < target) { }
        __threadfence();
    }
    __syncthreads();
}

// ---------------- init: zero deg/cur/barrier + dtype detection --------------
__global__ void k_init(const int* __restrict__ ei, const unsigned int* __restrict__ Mw) {
    int i = blockIdx.x * blockDim.x + threadIdx.x;
    if (i < NN) { g_deg[i] = 0; g_cur[i] = 0; }
    if (blockIdx.x == 0) {
        __shared__ int s_or, s_gt;
        if (threadIdx.x == 0) { s_or = 0; s_gt = 0; g_barc = 0; }
        __syncthreads();
        int t = threadIdx.x;
        if (ei[2 * t + 1] != 0) atomicOr(&s_or, 1);
        if (Mw[t] > 1u)         atomicOr(&s_gt, 1);
        __syncthreads();
        if (threadIdx.x == 0) { g_ei_is64 = (s_or == 0); g_m_is32 = (s_gt == 0); }
    }
}

// ---------------- CSC build: count + scan + fixup/dinv + bucket, one kernel -
__global__ void __launch_bounds__(NTH)
k_build(const int* __restrict__ ei) {
    const int tid = threadIdx.x, blk = blockIdx.x;
    const int gt = blk * NTH + tid;
    const int is64 = g_ei_is64;

    // --- phase A: degree count (grid-stride over edges) ---
    for (int e = gt; e < EE; e += NB * NTH) {
        int c = is64 ? ei[2 * (EE + e)] : ei[EE + e];
        atomicAdd(&g_deg[c], 1);
    }
    gbar(NB);

    // --- phase B: per-block inclusive scan + dinv; block sums to g_bsum ---
    {
        __shared__ int wsum[32];
        int lane = tid & 31, wid = tid >> 5;
        int i = gt;
        int v = (i < NN) ? g_deg[i] : 0;
        if (i < NN) g_dinv[i] = (v > 0) ? rsqrtf((float)v) : 0.0f;
        int x = v;
#pragma unroll
        for (int o = 1; o < 32; o <<= 1) {
            int t = __shfl_up_sync(0xffffffffu, x, o);
            if (lane >= o) x += t;
        }
        if (lane == 31) wsum[wid] = x;
        __syncthreads();
        if (wid == 0) {
            int s = wsum[lane];
#pragma unroll
            for (int o = 1; o < 32; o <<= 1) {
                int t = __shfl_up_sync(0xffffffffu, s, o);
                if (lane >= o) s += t;
            }
            wsum[lane] = s;
        }
        __syncthreads();
        int woff = (wid > 0) ? wsum[wid - 1] : 0;
        if (i < NN) g_off[i + 1] = woff + x;          // block-local inclusive
        if (tid == NTH - 1) g_bsum[blk] = woff + x;
    }
    gbar(2 * NB);

    // --- phase C: add block-prefix offsets ---
    {
        __shared__ int s_boff;
        if (tid == 0) {
            int acc = 0;
            for (int b2 = 0; b2 < blk; b2++) acc += g_bsum[b2];
            s_boff = acc;
        }
        __syncthreads();
        int i = gt;
        if (i < NN) g_off[i + 1] += s_boff;
        if (i == 0) g_off[0] = 0;
    }
    gbar(3 * NB);

    // --- phase D: bucket edges (grid-stride) ---
    for (int e = gt; e < EE; e += NB * NTH) {
        int r, c;
        if (is64) { r = ei[2 * e]; c = ei[2 * (EE + e)]; }
        else      { r = ei[e];     c = ei[EE + e]; }
        int p = atomicAdd(&g_cur[c], 1);
        g_src[g_off[c] + p] = r;
    }
}

// ---------------- x_tilde init (fp16, pre-scaled by dinv[row]) --------------
__global__ void k_xt0m(const float* __restrict__ x, const void* __restrict__ M) {
    int i = blockIdx.x * blockDim.x + threadIdx.x;   // over (N*D)/4
    if (i >= NN * DD / 4) return;
    uchar4 mv;
    if (g_m_is32) {
        int4 w = ((const int4*)M)[i];
        mv = make_uchar4((unsigned char)w.x, (unsigned char)w.y,
                         (unsigned char)w.z, (unsigned char)w.w);
    } else {
        mv = ((const uchar4*)M)[i];
    }
    ((uchar4*)g_M)[i] = mv;
    float dv = g_dinv[i >> 5];
    float4 xv = ((const float4*)x)[i];
    __half2 h01 = __floats2half2_rn(mv.x ? dv * xv.x : 0.0f,
                                    mv.y ? dv * xv.y : 0.0f);
    __half2 h23 = __floats2half2_rn(mv.z ? dv * xv.z : 0.0f,
                                    mv.w ? dv * xv.w : 0.0f);
    uint2 packed;
    packed.x = *(unsigned int*)&h01;
    packed.y = *(unsigned int*)&h23;
    ((uint2*)g_xt)[i] = packed;
}

// ---------------- SpMM: one warp per destination node (fp16 gather) ---------
// agg[c] = dinv[c] * sum_{src in col c} xt_scaled[src]; fp32 accumulate.
__global__ void k_spmm() {
    int warp = (blockIdx.x * blockDim.x + threadIdx.x) >> 5;
    if (warp >= NN) return;
    int lane = threadIdx.x & 31;
    int s = g_off[warp], t = g_off[warp + 1];
    const uint2* xt2 = (const uint2*)g_xt;   // 8B = 4 halfs per lane
    float4 acc = make_float4(0.f, 0.f, 0.f, 0.f);
    int i = s;
    for (; i + 8 <= t; i += 8) {
        uint2 rv[8];
#pragma unroll
        for (int u = 0; u < 8; u++) rv[u] = xt2[g_src[i + u] * 32 + lane];
#pragma unroll
        for (int u = 0; u < 8; u++) {
            float2 f01 = __half22float2(*(__half2*)&rv[u].x);
            float2 f23 = __half22float2(*(__half2*)&rv[u].y);
            acc.x += f01.x; acc.y += f01.y; acc.z += f23.x; acc.w += f23.y;
        }
    }
    for (; i + 4 <= t; i += 4) {
        uint2 rv[4];
#pragma unroll
        for (int u = 0; u < 4; u++) rv[u] = xt2[g_src[i + u] * 32 + lane];
#pragma unroll
        for (int u = 0; u < 4; u++) {
            float2 f01 = __half22float2(*(__half2*)&rv[u].x);
            float2 f23 = __half22float2(*(__half2*)&rv[u].y);
            acc.x += f01.x; acc.y += f01.y; acc.z += f23.x; acc.w += f23.y;
        }
    }
    for (; i < t; i++) {
        uint2 rv = xt2[g_src[i] * 32 + lane];
        float2 f01 = __half22float2(*(__half2*)&rv.x);
        float2 f23 = __half22float2(*(__half2*)&rv.y);
        acc.x += f01.x; acc.y += f01.y; acc.z += f23.x; acc.w += f23.y;
    }
    float dv = g_dinv[warp];
    acc.x *= dv; acc.y *= dv; acc.z *= dv; acc.w *= dv;
    ((float4*)g_agg)[warp * 32 + lane] = acc;
}

// ---------------- GEMM with packed f32x2 FMA ---------------------------------
// D[128 x NOUT] = A[128 x 128] @ W[NOUT x 128]^T, A = g_agg (g_h for FINAL).
// Hidden layers write ONLY next x_tilde (fp16, pre-scaled) or, layer 3, g_h.
template <int NOUT, bool FINAL>
__global__ void __launch_bounds__(256)
k_gemm(const float* __restrict__ W, const float* __restrict__ b,
       const float* __restrict__ bias, const float* __restrict__ x,
       float* __restrict__ out, int write_xt) {
    constexpr int NPAIR = NOUT / 32;
    __shared__ float sA[128 * 33];       // [r][kk] chunk
    __shared__ float sW[32 * 130];       // [kk][j] chunk, 8B-aligned pairs
    __shared__ float sB[128];
    int tid = threadIdx.x;
    int row0 = blockIdx.x * 128;
    int tr = tid >> 4, tc = tid & 15;

    if (tid < NOUT) sB[tid] = FINAL ? b[tid] : (b[tid] + bias[tid]);

    u64 acc[8][NPAIR];
#pragma unroll
    for (int ii = 0; ii < 8; ii++)
#pragma unroll
        for (int jj = 0; jj < NPAIR; jj++) acc[ii][jj] = 0ull;

    const float4* A4 = (const float4*)(FINAL ? g_h : g_agg);
    const float4* W4 = (const float4*)W;

    for (int kc = 0; kc < 4; kc++) {
        for (int t = tid; t < 128 * 8; t += 256) {
            int r = t >> 3, q = t & 7;
            float4 v = (row0 + r < NN) ? A4[(size_t)(row0 + r) * 32 + kc * 8 + q]
                                       : make_float4(0.f, 0.f, 0.f, 0.f);
            float* dst = &sA[r * 33 + q * 4];
            dst[0] = v.x; dst[1] = v.y; dst[2] = v.z; dst[3] = v.w;
        }
        for (int t = tid; t < NOUT * 8; t += 256) {
            int j = t >> 3, q = t & 7;
            float4 v = W4[(size_t)j * 32 + kc * 8 + q];
            int kk = q * 4;
            sW[(kk + 0) * 130 + j] = v.x;
            sW[(kk + 1) * 130 + j] = v.y;
            sW[(kk + 2) * 130 + j] = v.z;
            sW[(kk + 3) * 130 + j] = v.w;
        }
        __syncthreads();
#pragma unroll
        for (int kk = 0; kk < 32; kk++) {
            u64 a2[8], w2[NPAIR];
#pragma unroll
            for (int ii = 0; ii < 8; ii++)
                a2[ii] = pack2(sA[(tr + 16 * ii) * 33 + kk]);
#pragma unroll
            for (int jj = 0; jj < NPAIR; jj++)
                w2[jj] = *(const u64*)&sW[kk * 130 + 2 * tc + 32 * jj];
#pragma unroll
            for (int ii = 0; ii < 8; ii++)
#pragma unroll
                for (int jj = 0; jj < NPAIR; jj++)
                    fma2(acc[ii][jj], a2[ii], w2[jj]);
        }
        __syncthreads();
    }

#pragma unroll
    for (int ii = 0; ii < 8; ii++) {
        int r = row0 + tr + 16 * ii;
        if (r >= NN) continue;
        float dv = (!FINAL) ? g_dinv[r] : 0.f;
#pragma unroll
        for (int jj = 0; jj < NPAIR; jj++) {
            int j0 = 2 * tc + 32 * jj;
            float2 v = unpack2(acc[ii][jj]);
            if (FINAL) {
                v.x += sB[j0];
                v.y += sB[j0 + 1];
                *(float2*)&out[(size_t)r * OUTC + j0] = v;
            } else {
                v.x = fmaxf(v.x + sB[j0], 0.f);
                v.y = fmaxf(v.y + sB[j0 + 1], 0.f);
                size_t idx = (size_t)r * DD + j0;
                if (write_xt) {
                    unsigned char m0 = g_M[idx], m1 = g_M[idx + 1];
                    float2 xv = *(const float2*)&x[idx];
                    __half2 tv = __floats2half2_rn(dv * (m0 ? xv.x : v.x),
                                                   dv * (m1 ? xv.y : v.y));
                    *(__half2*)&g_xt[idx] = tv;
                } else {
                    *(float2*)&g_h[idx] = v;
                }
            }
        }
    }
}

// ---------------- launch ----------------------------------------------------
extern "C" void kernel_launch(void* const* d_in, const int* in_sizes, int n_in,
                              void* d_out, int out_size) {
    const int* ei = (const int*)d_in[0];   // [2,E], int32 or int64 (detected)
    const float* x = (const float*)d_in[2];
    const void*  M = d_in[3];              // bool or int32 (detected)
    const float* W1 = (const float*)d_in[4];
    const float* b1 = (const float*)d_in[5];
    const float* c1 = (const float*)d_in[6];
    const float* W2 = (const float*)d_in[7];
    const float* b2 = (const float*)d_in[8];
    const float* c2 = (const float*)d_in[9];
    const float* W3 = (const float*)d_in[10];
    const float* b3 = (const float*)d_in[11];
    const float* c3 = (const float*)d_in[12];
    const float* Wf = (const float*)d_in[13];
    const float* bf = (const float*)d_in[14];
    float* out = (float*)d_out;

    const int TB = 256;
    int nb_n = (NN + TB - 1) / TB;
    int nb_xt = (NN * DD / 4 + TB - 1) / TB;
    int nb_spmm = (NN * 32 + TB - 1) / TB;   // 1 warp per node
    int nb_gemm = (NN + 127) / 128;

    k_init<<<nb_n, TB>>>(ei, (const unsigned int*)M);
    k_build<<<NB, NTH>>>(ei);
    k_xt0m<<<nb_xt, TB>>>(x, M);

    k_spmm<<<nb_spmm, TB>>>();
    k_gemm<128, false><<<nb_gemm, TB>>>(W1, b1, c1, x, nullptr, 1);
    k_spmm<<<nb_spmm, TB>>>();
    k_gemm<128, false><<<nb_gemm, TB>>>(W2, b2, c2, x, nullptr, 1);
    k_spmm<<<nb_spmm, TB>>>();
    k_gemm<128, false><<<nb_gemm, TB>>>(W3, b3, c3, x, nullptr, 0);
    k_gemm<64, true><<<nb_gemm, TB>>>(Wf, bf, nullptr, nullptr, out, 0);
}

// round 12
// speedup vs baseline: 1.0947x; 1.0947x over previous
#include <cuda_runtime.h>
#include <cuda_fp16.h>
#include <math.h>
#include <stdint.h>

#define NN 50000
#define EE 800000
#define DD 128
#define OUTC 64
#define NBLK ((NN + 1023) / 1024)   // 49 scan blocks

typedef unsigned long long u64;

// ---------------- scratch (device globals; no allocation allowed) ----------
__device__ int   g_ei_is64;
__device__ int   g_m_is32;
__device__ int   g_deg[NN];
__device__ float g_dinv[NN];
__device__ int   g_off[NN + 1];
__device__ int   g_cur[NN];
__device__ int   g_bsum[64];
__device__ int   g_src[EE];
__device__ __half g_xt[NN * DD];    // x_tilde, fp16, pre-scaled by dinv[row]
__device__ __half g_x0[NN * DD];    // hrn(dinv*x) where mask=1, NaN where mask=0
__device__ float g_agg[NN * DD];    // aggregated messages (fp32)
__device__ float g_h[NN * DD];      // layer-3 activations

// ---------------- f32x2 packed math ----------------------------------------
__device__ __forceinline__ u64 pack2(float s) {
    u64 d;
    asm("mov.b64 %0, {%1, %1};" : "=l"(d) : "f"(s));
    return d;
}
__device__ __forceinline__ void fma2(u64& acc, u64 a, u64 b) {
    asm("fma.rn.f32x2 %0, %1, %2, %0;" : "+l"(acc) : "l"(a), "l"(b));
}
__device__ __forceinline__ float2 unpack2(u64 v) {
    float lo, hi;
    asm("mov.b64 {%0, %1}, %2;" : "=f"(lo), "=f"(hi) : "l"(v));
    return make_float2(lo, hi);
}

// ---------------- init: zero deg/cur + dtype detection ----------------------
__global__ void k_init(const int* __restrict__ ei, const unsigned int* __restrict__ Mw) {
    int i = blockIdx.x * blockDim.x + threadIdx.x;
    if (i < NN) { g_deg[i] = 0; g_cur[i] = 0; }
    if (blockIdx.x == 0) {
        __shared__ int s_or, s_gt;
        if (threadIdx.x == 0) { s_or = 0; s_gt = 0; }
        __syncthreads();
        int t = threadIdx.x;
        if (ei[2 * t + 1] != 0) atomicOr(&s_or, 1);
        if (Mw[t] > 1u)         atomicOr(&s_gt, 1);
        __syncthreads();
        if (threadIdx.x == 0) { g_ei_is64 = (s_or == 0); g_m_is32 = (s_gt == 0); }
    }
}

// ---------------- CSC build -------------------------------------------------
__global__ void k_count(const int* __restrict__ ei) {
    int e = blockIdx.x * blockDim.x + threadIdx.x;
    if (e >= EE) return;
    int c = g_ei_is64 ? ei[2 * (EE + e)] : ei[EE + e];
    atomicAdd(&g_deg[c], 1);
}

__global__ void k_scanA() {
    __shared__ int wsum[32];
    int tid = threadIdx.x, lane = tid & 31, wid = tid >> 5;
    int i = blockIdx.x * 1024 + tid;
    int v = (i < NN) ? g_deg[i] : 0;
    if (i < NN) g_dinv[i] = (v > 0) ? rsqrtf((float)v) : 0.0f;
    int x = v;
#pragma unroll
    for (int o = 1; o < 32; o <<= 1) {
        int t = __shfl_up_sync(0xffffffffu, x, o);
        if (lane >= o) x += t;
    }
    if (lane == 31) wsum[wid] = x;
    __syncthreads();
    if (wid == 0) {
        int s = wsum[lane];
#pragma unroll
        for (int o = 1; o < 32; o <<= 1) {
            int t = __shfl_up_sync(0xffffffffu, s, o);
            if (lane >= o) s += t;
        }
        wsum[lane] = s;
    }
    __syncthreads();
    int woff = (wid > 0) ? wsum[wid - 1] : 0;
    if (i < NN) g_off[i + 1] = woff + x;          // local inclusive
    if (tid == 1023) g_bsum[blockIdx.x] = woff + x;
}

__global__ void k_scanB() {
    __shared__ int s[64];
    int t = threadIdx.x;   // 64 threads
    s[t] = (t < NBLK) ? g_bsum[t] : 0;
    __syncthreads();
#pragma unroll
    for (int o = 1; o < 64; o <<= 1) {
        int v = (t >= o) ? s[t - o] : 0;
        __syncthreads();
        s[t] += v;
        __syncthreads();
    }
    g_bsum[t] = (t > 0) ? s[t - 1] : 0;           // exclusive
}

__global__ void k_scanC() {
    int i = blockIdx.x * 1024 + threadIdx.x;
    int add = g_bsum[blockIdx.x];
    if (i < NN) g_off[i + 1] += add;
    if (i == 0) g_off[0] = 0;
}

__global__ void k_bucket(const int* __restrict__ ei) {
    int e = blockIdx.x * blockDim.x + threadIdx.x;
    if (e >= EE) return;
    int r, c;
    if (g_ei_is64) { r = ei[2 * e]; c = ei[2 * (EE + e)]; }
    else           { r = ei[e];     c = ei[EE + e]; }
    int p = atomicAdd(&g_cur[c], 1);
    g_src[g_off[c] + p] = r;
}

// ---------------- x_tilde init + NaN-masked x0 (fp16) -----------------------
// g_xt: m ? hrn(dinv*x) : 0      (SpMM input, layer 1)
// g_x0: m ? hrn(dinv*x) : NaN    (epilogue select source, layers 1-2)
__global__ void k_xt0m(const float* __restrict__ x, const void* __restrict__ M) {
    int i = blockIdx.x * blockDim.x + threadIdx.x;   // over (N*D)/4
    if (i >= NN * DD / 4) return;
    uchar4 mv;
    if (g_m_is32) {
        int4 w = ((const int4*)M)[i];
        mv = make_uchar4((unsigned char)w.x, (unsigned char)w.y,
                         (unsigned char)w.z, (unsigned char)w.w);
    } else {
        mv = ((const uchar4*)M)[i];
    }
    float dv = g_dinv[i >> 5];
    float4 xv = ((const float4*)x)[i];
    float s0 = dv * xv.x, s1 = dv * xv.y, s2 = dv * xv.z, s3 = dv * xv.w;
    __half2 xt01 = __floats2half2_rn(mv.x ? s0 : 0.0f, mv.y ? s1 : 0.0f);
    __half2 xt23 = __floats2half2_rn(mv.z ? s2 : 0.0f, mv.w ? s3 : 0.0f);
    const float QNAN = __int_as_float(0x7fc00000);
    __half2 x001 = __floats2half2_rn(mv.x ? s0 : QNAN, mv.y ? s1 : QNAN);
    __half2 x023 = __floats2half2_rn(mv.z ? s2 : QNAN, mv.w ? s3 : QNAN);
    uint2 pxt, px0;
    pxt.x = *(unsigned int*)&xt01; pxt.y = *(unsigned int*)&xt23;
    px0.x = *(unsigned int*)&x001; px0.y = *(unsigned int*)&x023;
    ((uint2*)g_xt)[i] = pxt;
    ((uint2*)g_x0)[i] = px0;
}

// ---------------- SpMM: one warp per destination node (fp16 gather) ---------
// agg[c] = dinv[c] * sum_{src in col c} xt_scaled[src]; fp32 accumulate.
__global__ void k_spmm() {
    int warp = (blockIdx.x * blockDim.x + threadIdx.x) >> 5;
    if (warp >= NN) return;
    int lane = threadIdx.x & 31;
    int s = g_off[warp], t = g_off[warp + 1];
    const uint2* xt2 = (const uint2*)g_xt;   // 8B = 4 halfs per lane
    float4 acc = make_float4(0.f, 0.f, 0.f, 0.f);
    int i = s;
    for (; i + 8 <= t; i += 8) {
        uint2 rv[8];
#pragma unroll
        for (int u = 0; u < 8; u++) rv[u] = xt2[g_src[i + u] * 32 + lane];
#pragma unroll
        for (int u = 0; u < 8; u++) {
            float2 f01 = __half22float2(*(__half2*)&rv[u].x);
            float2 f23 = __half22float2(*(__half2*)&rv[u].y);
            acc.x += f01.x; acc.y += f01.y; acc.z += f23.x; acc.w += f23.y;
        }
    }
    for (; i + 4 <= t; i += 4) {
        uint2 rv[4];
#pragma unroll
        for (int u = 0; u < 4; u++) rv[u] = xt2[g_src[i + u] * 32 + lane];
#pragma unroll
        for (int u = 0; u < 4; u++) {
            float2 f01 = __half22float2(*(__half2*)&rv[u].x);
            float2 f23 = __half22float2(*(__half2*)&rv[u].y);
            acc.x += f01.x; acc.y += f01.y; acc.z += f23.x; acc.w += f23.y;
        }
    }
    for (; i < t; i++) {
        uint2 rv = xt2[g_src[i] * 32 + lane];
        float2 f01 = __half22float2(*(__half2*)&rv.x);
        float2 f23 = __half22float2(*(__half2*)&rv.y);
        acc.x += f01.x; acc.y += f01.y; acc.z += f23.x; acc.w += f23.y;
    }
    float dv = g_dinv[warp];
    acc.x *= dv; acc.y *= dv; acc.z *= dv; acc.w *= dv;
    ((float4*)g_agg)[warp * 32 + lane] = acc;
}

// ---------------- GEMM with packed f32x2 FMA ---------------------------------
// D[128 x NOUT] = A[128 x 128] @ W[NOUT x 128]^T, A = g_agg (g_h for FINAL).
// Hidden epilogue: xt_next = isnan(x0) ? dinv*relu(v+b) : x0   (fp16).
template <int NOUT, bool FINAL>
__global__ void __launch_bounds__(256)
k_gemm(const float* __restrict__ W, const float* __restrict__ b,
       const float* __restrict__ bias,
       float* __restrict__ out, int write_xt) {
    constexpr int NPAIR = NOUT / 32;
    __shared__ float sA[128 * 33];       // [r][kk] chunk
    __shared__ float sW[32 * 130];       // [kk][j] chunk, 8B-aligned pairs
    __shared__ float sB[128];
    int tid = threadIdx.x;
    int row0 = blockIdx.x * 128;
    int tr = tid >> 4, tc = tid & 15;

    if (tid < NOUT) sB[tid] = FINAL ? b[tid] : (b[tid] + bias[tid]);

    u64 acc[8][NPAIR];
#pragma unroll
    for (int ii = 0; ii < 8; ii++)
#pragma unroll
        for (int jj = 0; jj < NPAIR; jj++) acc[ii][jj] = 0ull;

    const float4* A4 = (const float4*)(FINAL ? g_h : g_agg);
    const float4* W4 = (const float4*)W;

    for (int kc = 0; kc < 4; kc++) {
        for (int t = tid; t < 128 * 8; t += 256) {
            int r = t >> 3, q = t & 7;
            float4 v = (row0 + r < NN) ? A4[(size_t)(row0 + r) * 32 + kc * 8 + q]
                                       : make_float4(0.f, 0.f, 0.f, 0.f);
            float* dst = &sA[r * 33 + q * 4];
            dst[0] = v.x; dst[1] = v.y; dst[2] = v.z; dst[3] = v.w;
        }
        for (int t = tid; t < NOUT * 8; t += 256) {
            int j = t >> 3, q = t & 7;
            float4 v = W4[(size_t)j * 32 + kc * 8 + q];
            int kk = q * 4;
            sW[(kk + 0) * 130 + j] = v.x;
            sW[(kk + 1) * 130 + j] = v.y;
            sW[(kk + 2) * 130 + j] = v.z;
            sW[(kk + 3) * 130 + j] = v.w;
        }
        __syncthreads();
#pragma unroll
        for (int kk = 0; kk < 32; kk++) {
            u64 a2[8], w2[NPAIR];
#pragma unroll
            for (int ii = 0; ii < 8; ii++)
                a2[ii] = pack2(sA[(tr + 16 * ii) * 33 + kk]);
#pragma unroll
            for (int jj = 0; jj < NPAIR; jj++)
                w2[jj] = *(const u64*)&sW[kk * 130 + 2 * tc + 32 * jj];
#pragma unroll
            for (int ii = 0; ii < 8; ii++)
#pragma unroll
                for (int jj = 0; jj < NPAIR; jj++)
                    fma2(acc[ii][jj], a2[ii], w2[jj]);
        }
        __syncthreads();
    }

#pragma unroll
    for (int ii = 0; ii < 8; ii++) {
        int r = row0 + tr + 16 * ii;
        if (r >= NN) continue;
        float dv = (!FINAL) ? g_dinv[r] : 0.f;
#pragma unroll
        for (int jj = 0; jj < NPAIR; jj++) {
            int j0 = 2 * tc + 32 * jj;
            float2 v = unpack2(acc[ii][jj]);
            if (FINAL) {
                v.x += sB[j0];
                v.y += sB[j0 + 1];
                *(float2*)&out[(size_t)r * OUTC + j0] = v;
            } else {
                v.x = fmaxf(v.x + sB[j0], 0.f);
                v.y = fmaxf(v.y + sB[j0 + 1], 0.f);
                size_t idx = (size_t)r * DD + j0;
                if (write_xt) {
                    // xt_next = isnan(x0) ? dinv*h : x0   (x0 already = hrn(dinv*x))
                    __half2 x0 = *(const __half2*)&g_x0[idx];
                    float2 x0f = __half22float2(x0);
                    float t0 = isnan(x0f.x) ? dv * v.x : x0f.x;
                    float t1 = isnan(x0f.y) ? dv * v.y : x0f.y;
                    *(__half2*)&g_xt[idx] = __floats2half2_rn(t0, t1);
                } else {
                    *(float2*)&g_h[idx] = v;
                }
            }
        }
    }
}

// ---------------- launch ----------------------------------------------------
extern "C" void kernel_launch(void* const* d_in, const int* in_sizes, int n_in,
                              void* d_out, int out_size) {
    const int* ei = (const int*)d_in[0];   // [2,E], int32 or int64 (detected)
    const float* x = (const float*)d_in[2];
    const void*  M = d_in[3];              // bool or int32 (detected)
    const float* W1 = (const float*)d_in[4];
    const float* b1 = (const float*)d_in[5];
    const float* c1 = (const float*)d_in[6];
    const float* W2 = (const float*)d_in[7];
    const float* b2 = (const float*)d_in[8];
    const float* c2 = (const float*)d_in[9];
    const float* W3 = (const float*)d_in[10];
    const float* b3 = (const float*)d_in[11];
    const float* c3 = (const float*)d_in[12];
    const float* Wf = (const float*)d_in[13];
    const float* bf = (const float*)d_in[14];
    float* out = (float*)d_out;

    const int TB = 256;
    int nb_n = (NN + TB - 1) / TB;
    int nb_e = (EE + TB - 1) / TB;
    int nb_xt = (NN * DD / 4 + TB - 1) / TB;
    int nb_spmm = (NN * 32 + TB - 1) / TB;   // 1 warp per node
    int nb_gemm = (NN + 127) / 128;

    k_init<<<nb_n, TB>>>(ei, (const unsigned int*)M);
    k_count<<<nb_e, TB>>>(ei);
    k_scanA<<<NBLK, 1024>>>();
    k_scanB<<<1, 64>>>();
    k_scanC<<<NBLK, 1024>>>();
    k_bucket<<<nb_e, TB>>>(ei);
    k_xt0m<<<nb_xt, TB>>>(x, M);

    k_spmm<<<nb_spmm, TB>>>();
    k_gemm<128, false><<<nb_gemm, TB>>>(W1, b1, c1, nullptr, 1);
    k_spmm<<<nb_spmm, TB>>>();
    k_gemm<128, false><<<nb_gemm, TB>>>(W2, b2, c2, nullptr, 1);
    k_spmm<<<nb_spmm, TB>>>();
    k_gemm<128, false><<<nb_gemm, TB>>>(W3, b3, c3, nullptr, 0);
    k_gemm<64, true><<<nb_gemm, TB>>>(Wf, bf, nullptr, out, 0);
}

// round 13
// speedup vs baseline: 1.1580x; 1.0578x over previous
#include <cuda_runtime.h>
#include <cuda_fp16.h>
#include <math.h>
#include <stdint.h>

#define NN 50000
#define EE 800000
#define DD 128
#define OUTC 64
#define NBLK ((NN + 1023) / 1024)   // 49 scan blocks

typedef unsigned long long u64;

// ---------------- scratch (device globals; no allocation allowed) ----------
__device__ int   g_ei_is64;
__device__ int   g_m_is32;
__device__ int   g_deg[NN];
__device__ float g_dinv[NN];
__device__ int   g_off[NN + 1];
__device__ int   g_bsum[64];
__device__ int   g_rank[EE];        // per-edge rank within its column
__device__ int   g_src[EE];
__device__ __half g_xt[NN * DD];    // x_tilde, fp16, pre-scaled by dinv[row]
__device__ __half g_x0[NN * DD];    // hrn(dinv*x) where mask=1, NaN where mask=0
__device__ __half g_agg[NN * DD];   // aggregated messages (fp16)
__device__ float g_h[NN * DD];      // layer-3 activations (fp32)

// ---------------- f32x2 packed math ----------------------------------------
__device__ __forceinline__ u64 pack2(float s) {
    u64 d;
    asm("mov.b64 %0, {%1, %1};" : "=l"(d) : "f"(s));
    return d;
}
__device__ __forceinline__ void fma2(u64& acc, u64 a, u64 b) {
    asm("fma.rn.f32x2 %0, %1, %2, %0;" : "+l"(acc) : "l"(a), "l"(b));
}
__device__ __forceinline__ float2 unpack2(u64 v) {
    float lo, hi;
    asm("mov.b64 {%0, %1}, %2;" : "=f"(lo), "=f"(hi) : "l"(v));
    return make_float2(lo, hi);
}

// ---------------- init: zero deg + dtype detection ---------------------------
__global__ void k_init(const int* __restrict__ ei, const unsigned int* __restrict__ Mw) {
    int i = blockIdx.x * blockDim.x + threadIdx.x;
    if (i < NN) g_deg[i] = 0;
    if (blockIdx.x == 0) {
        __shared__ int s_or, s_gt;
        if (threadIdx.x == 0) { s_or = 0; s_gt = 0; }
        __syncthreads();
        int t = threadIdx.x;
        if (ei[2 * t + 1] != 0) atomicOr(&s_or, 1);
        if (Mw[t] > 1u)         atomicOr(&s_gt, 1);
        __syncthreads();
        if (threadIdx.x == 0) { g_ei_is64 = (s_or == 0); g_m_is32 = (s_gt == 0); }
    }
}

// ---------------- CSC build: count assigns per-edge ranks --------------------
__global__ void k_count(const int* __restrict__ ei) {
    int e = blockIdx.x * blockDim.x + threadIdx.x;
    if (e >= EE) return;
    int c = g_ei_is64 ? ei[2 * (EE + e)] : ei[EE + e];
    g_rank[e] = atomicAdd(&g_deg[c], 1);
}

__global__ void k_scanA() {
    __shared__ int wsum[32];
    int tid = threadIdx.x, lane = tid & 31, wid = tid >> 5;
    int i = blockIdx.x * 1024 + tid;
    int v = (i < NN) ? g_deg[i] : 0;
    if (i < NN) g_dinv[i] = (v > 0) ? rsqrtf((float)v) : 0.0f;
    int x = v;
#pragma unroll
    for (int o = 1; o < 32; o <<= 1) {
        int t = __shfl_up_sync(0xffffffffu, x, o);
        if (lane >= o) x += t;
    }
    if (lane == 31) wsum[wid] = x;
    __syncthreads();
    if (wid == 0) {
        int s = wsum[lane];
#pragma unroll
        for (int o = 1; o < 32; o <<= 1) {
            int t = __shfl_up_sync(0xffffffffu, s, o);
            if (lane >= o) s += t;
        }
        wsum[lane] = s;
    }
    __syncthreads();
    int woff = (wid > 0) ? wsum[wid - 1] : 0;
    if (i < NN) g_off[i + 1] = woff + x;          // block-local inclusive
    if (tid == 1023) g_bsum[blockIdx.x] = woff + x;
}

__global__ void k_scanB() {
    __shared__ int s[64];
    int t = threadIdx.x;   // 64 threads
    s[t] = (t < NBLK) ? g_bsum[t] : 0;
    __syncthreads();
#pragma unroll
    for (int o = 1; o < 64; o <<= 1) {
        int v = (t >= o) ? s[t - o] : 0;
        __syncthreads();
        s[t] += v;
        __syncthreads();
    }
    g_bsum[t] = (t > 0) ? s[t - 1] : 0;           // exclusive
}

// ---------------- fix offsets (scanC) + x_tilde/x0 init, one kernel ----------
// gid < NN: add block-prefix to g_off. All gids: fp16 xt/x0 init.
__global__ void k_fix_xt(const float* __restrict__ x, const void* __restrict__ M) {
    int gid = blockIdx.x * blockDim.x + threadIdx.x;
    if (gid < NN) g_off[gid + 1] += g_bsum[gid >> 10];
    if (gid == 0) g_off[0] = 0;
    int i = gid;                                   // over (N*D)/4
    if (i >= NN * DD / 4) return;
    uchar4 mv;
    if (g_m_is32) {
        int4 w = ((const int4*)M)[i];
        mv = make_uchar4((unsigned char)w.x, (unsigned char)w.y,
                         (unsigned char)w.z, (unsigned char)w.w);
    } else {
        mv = ((const uchar4*)M)[i];
    }
    float dv = g_dinv[i >> 5];
    float4 xv = ((const float4*)x)[i];
    float s0 = dv * xv.x, s1 = dv * xv.y, s2 = dv * xv.z, s3 = dv * xv.w;
    __half2 xt01 = __floats2half2_rn(mv.x ? s0 : 0.0f, mv.y ? s1 : 0.0f);
    __half2 xt23 = __floats2half2_rn(mv.z ? s2 : 0.0f, mv.w ? s3 : 0.0f);
    const float QNAN = __int_as_float(0x7fc00000);
    __half2 x001 = __floats2half2_rn(mv.x ? s0 : QNAN, mv.y ? s1 : QNAN);
    __half2 x023 = __floats2half2_rn(mv.z ? s2 : QNAN, mv.w ? s3 : QNAN);
    uint2 pxt, px0;
    pxt.x = *(unsigned int*)&xt01; pxt.y = *(unsigned int*)&xt23;
    px0.x = *(unsigned int*)&x001; px0.y = *(unsigned int*)&x023;
    ((uint2*)g_xt)[i] = pxt;
    ((uint2*)g_x0)[i] = px0;
}

// ---------------- bucket: pure scattered store (no atomics) ------------------
__global__ void k_bucket(const int* __restrict__ ei) {
    int e = blockIdx.x * blockDim.x + threadIdx.x;
    if (e >= EE) return;
    int r, c;
    if (g_ei_is64) { r = ei[2 * e]; c = ei[2 * (EE + e)]; }
    else           { r = ei[e];     c = ei[EE + e]; }
    g_src[g_off[c] + g_rank[e]] = r;
}

// ---------------- SpMM: one warp per destination node (fp16 in/out) ----------
__global__ void k_spmm() {
    int warp = (blockIdx.x * blockDim.x + threadIdx.x) >> 5;
    if (warp >= NN) return;
    int lane = threadIdx.x & 31;
    int s = g_off[warp], t = g_off[warp + 1];
    const uint2* xt2 = (const uint2*)g_xt;   // 8B = 4 halfs per lane
    float4 acc = make_float4(0.f, 0.f, 0.f, 0.f);
    int i = s;
    for (; i + 8 <= t; i += 8) {
        uint2 rv[8];
#pragma unroll
        for (int u = 0; u < 8; u++) rv[u] = xt2[g_src[i + u] * 32 + lane];
#pragma unroll
        for (int u = 0; u < 8; u++) {
            float2 f01 = __half22float2(*(__half2*)&rv[u].x);
            float2 f23 = __half22float2(*(__half2*)&rv[u].y);
            acc.x += f01.x; acc.y += f01.y; acc.z += f23.x; acc.w += f23.y;
        }
    }
    for (; i + 4 <= t; i += 4) {
        uint2 rv[4];
#pragma unroll
        for (int u = 0; u < 4; u++) rv[u] = xt2[g_src[i + u] * 32 + lane];
#pragma unroll
        for (int u = 0; u < 4; u++) {
            float2 f01 = __half22float2(*(__half2*)&rv[u].x);
            float2 f23 = __half22float2(*(__half2*)&rv[u].y);
            acc.x += f01.x; acc.y += f01.y; acc.z += f23.x; acc.w += f23.y;
        }
    }
    for (; i < t; i++) {
        uint2 rv = xt2[g_src[i] * 32 + lane];
        float2 f01 = __half22float2(*(__half2*)&rv.x);
        float2 f23 = __half22float2(*(__half2*)&rv.y);
        acc.x += f01.x; acc.y += f01.y; acc.z += f23.x; acc.w += f23.y;
    }
    float dv = g_dinv[warp];
    __half2 o01 = __floats2half2_rn(dv * acc.x, dv * acc.y);
    __half2 o23 = __floats2half2_rn(dv * acc.z, dv * acc.w);
    uint2 p;
    p.x = *(unsigned int*)&o01;
    p.y = *(unsigned int*)&o23;
    ((uint2*)g_agg)[warp * 32 + lane] = p;
}

// ---------------- GEMM with packed f32x2 FMA ---------------------------------
// D[128 x NOUT] = A[128 x 128] @ W[NOUT x 128]^T.
// A = g_agg (fp16, converted in loader) or g_h (fp32) for FINAL.
template <int NOUT, bool FINAL>
__global__ void __launch_bounds__(256)
k_gemm(const float* __restrict__ W, const float* __restrict__ b,
       const float* __restrict__ bias,
       float* __restrict__ out, int write_xt) {
    constexpr int NPAIR = NOUT / 32;
    __shared__ float sA[128 * 33];       // [r][kk] chunk
    __shared__ float sW[32 * 130];       // [kk][j] chunk, 8B-aligned pairs
    __shared__ float sB[128];
    int tid = threadIdx.x;
    int row0 = blockIdx.x * 128;
    int tr = tid >> 4, tc = tid & 15;

    if (tid < NOUT) sB[tid] = FINAL ? b[tid] : (b[tid] + bias[tid]);

    u64 acc[8][NPAIR];
#pragma unroll
    for (int ii = 0; ii < 8; ii++)
#pragma unroll
        for (int jj = 0; jj < NPAIR; jj++) acc[ii][jj] = 0ull;

    const float4* W4 = (const float4*)W;

    for (int kc = 0; kc < 4; kc++) {
        if (FINAL) {
            const float4* A4 = (const float4*)g_h;
            for (int t = tid; t < 128 * 8; t += 256) {
                int r = t >> 3, q = t & 7;
                float4 v = (row0 + r < NN) ? A4[(size_t)(row0 + r) * 32 + kc * 8 + q]
                                           : make_float4(0.f, 0.f, 0.f, 0.f);
                float* dst = &sA[r * 33 + q * 4];
                dst[0] = v.x; dst[1] = v.y; dst[2] = v.z; dst[3] = v.w;
            }
        } else {
            const uint2* A2 = (const uint2*)g_agg;
            for (int t = tid; t < 128 * 8; t += 256) {
                int r = t >> 3, q = t & 7;
                uint2 v = (row0 + r < NN) ? A2[(size_t)(row0 + r) * 32 + kc * 8 + q]
                                          : make_uint2(0u, 0u);
                float2 f01 = __half22float2(*(__half2*)&v.x);
                float2 f23 = __half22float2(*(__half2*)&v.y);
                float* dst = &sA[r * 33 + q * 4];
                dst[0] = f01.x; dst[1] = f01.y; dst[2] = f23.x; dst[3] = f23.y;
            }
        }
        for (int t = tid; t < NOUT * 8; t += 256) {
            int j = t >> 3, q = t & 7;
            float4 v = W4[(size_t)j * 32 + kc * 8 + q];
            int kk = q * 4;
            sW[(kk + 0) * 130 + j] = v.x;
            sW[(kk + 1) * 130 + j] = v.y;
            sW[(kk + 2) * 130 + j] = v.z;
            sW[(kk + 3) * 130 + j] = v.w;
        }
        __syncthreads();
#pragma unroll
        for (int kk = 0; kk < 32; kk++) {
            u64 a2[8], w2[NPAIR];
#pragma unroll
            for (int ii = 0; ii < 8; ii++)
                a2[ii] = pack2(sA[(tr + 16 * ii) * 33 + kk]);
#pragma unroll
            for (int jj = 0; jj < NPAIR; jj++)
                w2[jj] = *(const u64*)&sW[kk * 130 + 2 * tc + 32 * jj];
#pragma unroll
            for (int ii = 0; ii < 8; ii++)
#pragma unroll
                for (int jj = 0; jj < NPAIR; jj++)
                    fma2(acc[ii][jj], a2[ii], w2[jj]);
        }
        __syncthreads();
    }

#pragma unroll
    for (int ii = 0; ii < 8; ii++) {
        int r = row0 + tr + 16 * ii;
        if (r >= NN) continue;
        float dv = (!FINAL) ? g_dinv[r] : 0.f;
#pragma unroll
        for (int jj = 0; jj < NPAIR; jj++) {
            int j0 = 2 * tc + 32 * jj;
            float2 v = unpack2(acc[ii][jj]);
            if (FINAL) {
                v.x += sB[j0];
                v.y += sB[j0 + 1];
                *(float2*)&out[(size_t)r * OUTC + j0] = v;
            } else {
                v.x = fmaxf(v.x + sB[j0], 0.f);
                v.y = fmaxf(v.y + sB[j0 + 1], 0.f);
                size_t idx = (size_t)r * DD + j0;
                if (write_xt) {
                    // xt_next = isnan(x0) ? dinv*h : x0   (x0 already = hrn(dinv*x))
                    __half2 x0 = *(const __half2*)&g_x0[idx];
                    float2 x0f = __half22float2(x0);
                    float t0 = isnan(x0f.x) ? dv * v.x : x0f.x;
                    float t1 = isnan(x0f.y) ? dv * v.y : x0f.y;
                    *(__half2*)&g_xt[idx] = __floats2half2_rn(t0, t1);
                } else {
                    *(float2*)&g_h[idx] = v;
                }
            }
        }
    }
}

// ---------------- launch ----------------------------------------------------
extern "C" void kernel_launch(void* const* d_in, const int* in_sizes, int n_in,
                              void* d_out, int out_size) {
    const int* ei = (const int*)d_in[0];   // [2,E], int32 or int64 (detected)
    const float* x = (const float*)d_in[2];
    const void*  M = d_in[3];              // bool or int32 (detected)
    const float* W1 = (const float*)d_in[4];
    const float* b1 = (const float*)d_in[5];
    const float* c1 = (const float*)d_in[6];
    const float* W2 = (const float*)d_in[7];
    const float* b2 = (const float*)d_in[8];
    const float* c2 = (const float*)d_in[9];
    const float* W3 = (const float*)d_in[10];
    const float* b3 = (const float*)d_in[11];
    const float* c3 = (const float*)d_in[12];
    const float* Wf = (const float*)d_in[13];
    const float* bf = (const float*)d_in[14];
    float* out = (float*)d_out;

    const int TB = 256;
    int nb_n = (NN + TB - 1) / TB;
    int nb_e = (EE + TB - 1) / TB;
    int nb_xt = (NN * DD / 4 + TB - 1) / TB;
    int nb_spmm = (NN * 32 + TB - 1) / TB;   // 1 warp per node
    int nb_gemm = (NN + 127) / 128;

    k_init<<<nb_n, TB>>>(ei, (const unsigned int*)M);
    k_count<<<nb_e, TB>>>(ei);
    k_scanA<<<NBLK, 1024>>>();
    k_scanB<<<1, 64>>>();
    k_fix_xt<<<nb_xt, TB>>>(x, M);
    k_bucket<<<nb_e, TB>>>(ei);

    k_spmm<<<nb_spmm, TB>>>();
    k_gemm<128, false><<<nb_gemm, TB>>>(W1, b1, c1, nullptr, 1);
    k_spmm<<<nb_spmm, TB>>>();
    k_gemm<128, false><<<nb_gemm, TB>>>(W2, b2, c2, nullptr, 1);
    k_spmm<<<nb_spmm, TB>>>();
    k_gemm<128, false><<<nb_gemm, TB>>>(W3, b3, c3, nullptr, 0);
    k_gemm<64, true><<<nb_gemm, TB>>>(Wf, bf, nullptr, out, 0);
}